// round 13
// baseline (speedup 1.0000x reference)
#include <cuda_runtime.h>
#include <math.h>
#include <stdint.h>

#define DIM 128
#define MAXN 50000
#define MAXE 1600000
#define BM 128
#define NT 256
// A staging: [4 ks][8 mt][2 g][32 t][4 floats] per buffer = 8192 floats = 32KB
#define AS_FLOATS 8192
#define SMEM_TC (2 * AS_FLOATS * 4)     // 64KB
#define WPK_FLOATS (16 * 16 * 32 * 4)   // one packed weight: 32768 floats

// scratch (device globals; allocation-free rule)
__device__ float g_H  [(size_t)MAXN * DIM];
__device__ float g_X  [(size_t)MAXN * DIM];
__device__ float g_AGG[(size_t)MAXN * DIM];
__device__ float g_OUT[(size_t)MAXN * DIM];
__device__ float g_Z  [(size_t)MAXN * DIM];
__device__ float g_RX [(size_t)MAXN * DIM];
__device__ float g_WP [10 * WPK_FLOATS];
__device__ int   g_off [MAXN + 1];
__device__ int   g_head[MAXN];
__device__ int   g_ecol[MAXE];
__device__ float g_eval[MAXE];

// ---------------- helpers ----------------------------------------------------
__device__ __forceinline__ uint32_t tf32_hi(float x) {
    uint32_t r; asm("cvt.rna.tf32.f32 %0, %1;" : "=r"(r) : "f"(x)); return r;
}
__device__ __forceinline__ void split_tf32(float v, float& h, float& l) {
    uint32_t hb = tf32_hi(v);
    float hf = __uint_as_float(hb);
    h = hf;
    l = __uint_as_float(tf32_hi(v - hf));
}
__device__ __forceinline__ void mma8(float* c,
                                     uint32_t a0, uint32_t a1, uint32_t a2, uint32_t a3,
                                     uint32_t b0, uint32_t b1) {
    asm("mma.sync.aligned.m16n8k8.row.col.f32.tf32.tf32.f32 "
        "{%0,%1,%2,%3}, {%4,%5,%6,%7}, {%8,%9}, {%0,%1,%2,%3};"
        : "+f"(c[0]), "+f"(c[1]), "+f"(c[2]), "+f"(c[3])
        : "r"(a0), "r"(a1), "r"(a2), "r"(a3), "r"(b0), "r"(b1));
}
__device__ __forceinline__ float sigf(float x) { return 1.f / (1.f + __expf(-x)); }

// ---------------- weight pack kernel -----------------------------------------
// W[k][n] (128x128 row-major, k-major) -> fragment order with h/l split.
// item (ks, nt, t): b0 = W[8ks + t%4][8nt + t/4], b1 = W[8ks+4+t%4][8nt + t/4]
// store float4 {b0h, b0l, b1h, b1l} at ((ks*16+nt)*32+t)*4
struct WPtrs { const float* p[10]; };
__global__ void pack_w_kernel(WPtrs wp, float* __restrict__ dst) {
    const float* W = wp.p[blockIdx.x];
    float* d = dst + (size_t)blockIdx.x * WPK_FLOATS;
    for (int idx = threadIdx.x; idx < 16 * 16 * 32; idx += blockDim.x) {
        int t  = idx & 31;
        int nt = (idx >> 5) & 15;
        int ks = idx >> 9;
        int k0 = ks * 8 + (t & 3);
        int n  = nt * 8 + (t >> 2);
        float b0 = W[k0 * DIM + n];
        float b1 = W[(k0 + 4) * DIM + n];
        float h0, l0, h1, l1;
        split_tf32(b0, h0, l0);
        split_tf32(b1, h1, l1);
        *(float4*)(d + (size_t)idx * 4) = make_float4(h0, l0, h1, l1);
    }
}

// ---------------- tensor-core GEMM -------------------------------------------
// C[M x 128] = A[M x K] @ W[K x 128] + epilogue; K = NCH*32 (NCH=4 or 8).
// NCH=8: A=[A0|A1], packed W = [Wp0;Wp1]. 3xTF32: AhBh + AhBl + AlBh.
// 8 warps: wm = warp>>2 (2), wn = warp&3 (4). Warp tile 64(m) x 32(n).
template<int EPI, int NCH>
__global__ void __launch_bounds__(NT, 2)
gemm_tc(const float* __restrict__ A0, const float* __restrict__ A1,
        const float* __restrict__ Wp0, const float* __restrict__ Wp1,
        const float* __restrict__ b1, const float* __restrict__ b2,
        const float* __restrict__ aux1, const float* __restrict__ aux2,
        float* __restrict__ out, int nrows)
{
    extern __shared__ float As[];      // [2][AS_FLOATS]
    const int t = threadIdx.x;
    const int lane = t & 31;
    const int warp = t >> 5;
    const int wm = warp >> 2;          // 0..1
    const int wn = warp & 3;           // 0..3
    const int row0 = blockIdx.x * BM;

    float acc[4][4][4];
    #pragma unroll
    for (int i = 0; i < 4; i++)
        #pragma unroll
        for (int j = 0; j < 4; j++)
            #pragma unroll
            for (int q = 0; q < 4; q++) acc[i][j][q] = 0.f;

    // stager regs: 4 float4 per chunk (1024 float4 / 256 threads)
    float4 sv[4];

    auto ldA = [&](int cc) {
        const float* src = (NCH == 8 && cc >= 4) ? A1 : A0;
        int kb = ((NCH == 8) ? (cc & 3) : cc) * 32;
        #pragma unroll
        for (int j = 0; j < 4; j++) {
            int idx = t + j * NT;
            int r = idx >> 3;          // 0..127
            int c4 = idx & 7;          // float4 within 32-k chunk
            if (row0 + r < nrows)
                sv[j] = *(const float4*)(src + (size_t)(row0 + r) * DIM + kb + c4 * 4);
            else
                sv[j] = make_float4(0.f, 0.f, 0.f, 0.f);
        }
    };
    auto stsA = [&](int buf) {
        float* d = As + buf * AS_FLOATS;
        #pragma unroll
        for (int j = 0; j < 4; j++) {
            int idx = t + j * NT;
            int r = idx >> 3;
            int c4 = idx & 7;
            int ks = c4 >> 1;          // 0..3
            int g  = c4 & 1;           // k-half within kstep
            int L  = (r & 7) * 4;      // lane base
            int e  = (r >> 3) & 1;     // row-half (a0 vs a1)
            int mt = r >> 4;           // 0..7
            int fbase = (((ks * 8 + mt) * 2 + g) * 32);
            float v[4] = {sv[j].x, sv[j].y, sv[j].z, sv[j].w};
            #pragma unroll
            for (int i = 0; i < 4; i++) {
                float h, l;
                split_tf32(v[i], h, l);
                *(float2*)(d + (size_t)(fbase + L + i) * 4 + e * 2) = make_float2(h, l);
            }
        }
    };

    ldA(0);
    stsA(0);

    for (int cc = 0; cc < NCH; cc++) {
        __syncthreads();
        if (cc + 1 < NCH) ldA(cc + 1);
        const float* sb = As + (cc & 1) * AS_FLOATS;
        const float* Wp = (NCH == 8 && cc >= 4) ? Wp1 : Wp0;
        int ccl = (NCH == 8) ? (cc & 3) : cc;
        #pragma unroll
        for (int ks = 0; ks < 4; ks++) {
            int ksg = ccl * 4 + ks;
            uint4 bq[4];
            #pragma unroll
            for (int nt = 0; nt < 4; nt++)
                bq[nt] = *(const uint4*)(Wp + (size_t)(((ksg * 16 + wn * 4 + nt) * 32 + lane)) * 4);
            #pragma unroll
            for (int mt = 0; mt < 4; mt++) {
                int mt_g = wm * 4 + mt;
                uint4 q0 = *(const uint4*)(sb + (size_t)(((ks * 8 + mt_g) * 2 + 0) * 32 + lane) * 4);
                uint4 q1 = *(const uint4*)(sb + (size_t)(((ks * 8 + mt_g) * 2 + 1) * 32 + lane) * 4);
                #pragma unroll
                for (int nt = 0; nt < 4; nt++) {
                    // h*h
                    mma8(acc[mt][nt], q0.x, q0.z, q1.x, q1.z, bq[nt].x, bq[nt].z);
                    // h*l
                    mma8(acc[mt][nt], q0.x, q0.z, q1.x, q1.z, bq[nt].y, bq[nt].w);
                    // l*h
                    mma8(acc[mt][nt], q0.y, q0.w, q1.y, q1.w, bq[nt].x, bq[nt].z);
                }
            }
        }
        if (cc + 1 < NCH) stsA((cc + 1) & 1);
    }

    // ---------------- epilogue ----------------
    #pragma unroll
    for (int nt = 0; nt < 4; nt++) {
        int col = wn * 32 + nt * 8 + 2 * (lane & 3);
        float2 bb = *(const float2*)(b1 + col);
        if (b2 != nullptr) {
            float2 b2v = *(const float2*)(b2 + col);
            bb.x += b2v.x; bb.y += b2v.y;
        }
        #pragma unroll
        for (int mt = 0; mt < 4; mt++) {
            #pragma unroll
            for (int half = 0; half < 2; half++) {
                int m = row0 + wm * 64 + mt * 16 + (lane >> 2) + half * 8;
                if (m >= nrows) continue;
                float vx = acc[mt][nt][half * 2 + 0] + bb.x;
                float vy = acc[mt][nt][half * 2 + 1] + bb.y;
                float2 o;
                if (EPI == 0) {
                    o = make_float2(fmaxf(vx, 0.f), fmaxf(vy, 0.f));
                } else if (EPI == 1) {
                    o = make_float2(vx, vy);
                } else if (EPI == 2) {
                    o = make_float2(sigf(vx), sigf(vy));
                    if (aux1 != nullptr) {
                        float2 xv = *(const float2*)(aux1 + (size_t)m * DIM + col);
                        o.x *= xv.x; o.y *= xv.y;
                    }
                } else {  // EPI == 3: y = (1-z)*x + z*tanh(v)
                    float2 zv = *(const float2*)(aux1 + (size_t)m * DIM + col);
                    float2 xv = *(const float2*)(aux2 + (size_t)m * DIM + col);
                    o.x = (1.f - zv.x) * xv.x + zv.x * tanhf(vx);
                    o.y = (1.f - zv.y) * xv.y + zv.y * tanhf(vy);
                }
                *(float2*)(out + (size_t)m * DIM + col) = o;
            }
        }
    }
}

// ---------------- CSR build + gather (unchanged, proven) ---------------------
__global__ void hist_kernel(const int* __restrict__ rows, int* __restrict__ cnt, int E) {
    int e = blockIdx.x * blockDim.x + threadIdx.x;
    if (e < E) atomicAdd(&cnt[__ldg(rows + e)], 1);
}

__global__ void __launch_bounds__(1024)
scan_kernel(int* __restrict__ cnt, int* __restrict__ head, int n) {
    __shared__ int wsum[32];
    __shared__ int carry;
    const int tid = threadIdx.x;
    const int lane = tid & 31, w = tid >> 5;
    if (tid == 0) carry = 0;
    __syncthreads();
    for (int base = 0; base < n; base += 1024) {
        int i = base + tid;
        int v = (i < n) ? cnt[i] : 0;
        int x = v;
        #pragma unroll
        for (int d = 1; d < 32; d <<= 1) {
            int y = __shfl_up_sync(~0u, x, d);
            if (lane >= d) x += y;
        }
        if (lane == 31) wsum[w] = x;
        __syncthreads();
        if (w == 0) {
            int s = wsum[lane];
            #pragma unroll
            for (int d = 1; d < 32; d <<= 1) {
                int y = __shfl_up_sync(~0u, s, d);
                if (lane >= d) s += y;
            }
            wsum[lane] = s;
        }
        __syncthreads();
        int incl = x + (w > 0 ? wsum[w - 1] : 0) + carry;
        int excl = incl - v;
        if (i < n) { cnt[i] = excl; head[i] = excl; }
        __syncthreads();
        if (tid == 1023) carry = incl;
        __syncthreads();
    }
    if (tid == 0) cnt[n] = carry;
}

__global__ void bucket_kernel(const int* __restrict__ rows, const int* __restrict__ cols,
                              const float* __restrict__ vals, int* __restrict__ head,
                              int* __restrict__ ecol, float* __restrict__ eval, int E) {
    int e = blockIdx.x * blockDim.x + threadIdx.x;
    if (e < E) {
        int p = atomicAdd(&head[__ldg(rows + e)], 1);
        ecol[p] = __ldg(cols + e);
        eval[p] = __ldg(vals + e);
    }
}

__global__ void __launch_bounds__(256)
gather_kernel(const int* __restrict__ off, const int* __restrict__ ecol,
              const float* __restrict__ eval, const float* __restrict__ X,
              float* __restrict__ AGG, int n)
{
    int node = blockIdx.x * 8 + (threadIdx.x >> 5);
    int lane = threadIdx.x & 31;
    if (node >= n) return;
    int j   = __ldg(off + node);
    int end = __ldg(off + node + 1);
    float4 acc = make_float4(0.f, 0.f, 0.f, 0.f);
    for (; j + 1 < end; j += 2) {
        int   c0 = __ldg(ecol + j),     c1 = __ldg(ecol + j + 1);
        float v0 = __ldg(eval + j),     v1 = __ldg(eval + j + 1);
        float4 x0 = reinterpret_cast<const float4*>(X + (size_t)c0 * DIM)[lane];
        float4 x1 = reinterpret_cast<const float4*>(X + (size_t)c1 * DIM)[lane];
        acc.x = fmaf(v0, x0.x, acc.x); acc.y = fmaf(v0, x0.y, acc.y);
        acc.z = fmaf(v0, x0.z, acc.z); acc.w = fmaf(v0, x0.w, acc.w);
        acc.x = fmaf(v1, x1.x, acc.x); acc.y = fmaf(v1, x1.y, acc.y);
        acc.z = fmaf(v1, x1.z, acc.z); acc.w = fmaf(v1, x1.w, acc.w);
    }
    if (j < end) {
        int   c0 = __ldg(ecol + j);
        float v0 = __ldg(eval + j);
        float4 x0 = reinterpret_cast<const float4*>(X + (size_t)c0 * DIM)[lane];
        acc.x = fmaf(v0, x0.x, acc.x); acc.y = fmaf(v0, x0.y, acc.y);
        acc.z = fmaf(v0, x0.z, acc.z); acc.w = fmaf(v0, x0.w, acc.w);
    }
    reinterpret_cast<float4*>(AGG + (size_t)node * DIM)[lane] = acc;
}

// ---------------- launch -----------------------------------------------------
extern "C" void kernel_launch(void* const* d_in, const int* in_sizes, int n_in,
                              void* d_out, int out_size)
{
    const float* x_in = (const float*)d_in[0];
    const int*   rows = (const int*)d_in[1];
    const int*   cols = (const int*)d_in[2];
    const float* vals = (const float*)d_in[3];
    const float* m1W1 = (const float*)d_in[4];
    const float* m1b1 = (const float*)d_in[5];
    const float* m1W2 = (const float*)d_in[6];
    const float* m1b2 = (const float*)d_in[7];
    const float* m2W1 = (const float*)d_in[8];
    const float* m2b1 = (const float*)d_in[9];
    const float* m2W2 = (const float*)d_in[10];
    const float* m2b2 = (const float*)d_in[11];
    const float* Wu1 = (const float*)d_in[12];
    const float* bu1 = (const float*)d_in[13];
    const float* Wu2 = (const float*)d_in[14];
    const float* bu2 = (const float*)d_in[15];
    const float* Wr1 = (const float*)d_in[16];
    const float* br1 = (const float*)d_in[17];
    const float* Wr2 = (const float*)d_in[18];
    const float* br2 = (const float*)d_in[19];
    const float* Wo1 = (const float*)d_in[20];
    const float* bo1 = (const float*)d_in[21];
    const float* Wo2 = (const float*)d_in[22];
    const float* bo2 = (const float*)d_in[23];

    int n = in_sizes[0] / DIM;
    int E = in_sizes[1];
    float* y = (float*)d_out;

    float *H, *X, *AGG, *OUT, *Z, *RX, *EVAL, *WP;
    int *OFF, *HEAD, *ECOL;
    cudaGetSymbolAddress((void**)&H, g_H);
    cudaGetSymbolAddress((void**)&X, g_X);
    cudaGetSymbolAddress((void**)&AGG, g_AGG);
    cudaGetSymbolAddress((void**)&OUT, g_OUT);
    cudaGetSymbolAddress((void**)&Z, g_Z);
    cudaGetSymbolAddress((void**)&RX, g_RX);
    cudaGetSymbolAddress((void**)&WP, g_WP);
    cudaGetSymbolAddress((void**)&OFF, g_off);
    cudaGetSymbolAddress((void**)&HEAD, g_head);
    cudaGetSymbolAddress((void**)&ECOL, g_ecol);
    cudaGetSymbolAddress((void**)&EVAL, g_eval);

    cudaFuncSetAttribute(gemm_tc<0, 4>, cudaFuncAttributeMaxDynamicSharedMemorySize, SMEM_TC);
    cudaFuncSetAttribute(gemm_tc<1, 4>, cudaFuncAttributeMaxDynamicSharedMemorySize, SMEM_TC);
    cudaFuncSetAttribute(gemm_tc<2, 8>, cudaFuncAttributeMaxDynamicSharedMemorySize, SMEM_TC);
    cudaFuncSetAttribute(gemm_tc<3, 8>, cudaFuncAttributeMaxDynamicSharedMemorySize, SMEM_TC);

    int nb = (n + BM - 1) / BM;
    int eb = (E + 255) / 256;

    WPtrs wp;
    wp.p[0] = m1W1; wp.p[1] = m1W2; wp.p[2] = m2W1; wp.p[3] = m2W2;
    wp.p[4] = Wu1;  wp.p[5] = Wu2;  wp.p[6] = Wr1;  wp.p[7] = Wr2;
    wp.p[8] = Wo1;  wp.p[9] = Wo2;

    // ---- weight pack + CSR build ----
    pack_w_kernel<<<10, NT>>>(wp, WP);
    cudaMemsetAsync(OFF, 0, (size_t)(n + 1) * sizeof(int));
    hist_kernel<<<eb, 256>>>(rows, OFF, E);
    scan_kernel<<<1, 1024>>>(OFF, HEAD, n);
    bucket_kernel<<<eb, 256>>>(rows, cols, vals, HEAD, ECOL, EVAL, E);

    const float* WP0 = WP;
    // H = relu(x_in @ m1W1 + b1); X = H @ m1W2 + b2
    gemm_tc<0, 4><<<nb, NT, SMEM_TC>>>(x_in, nullptr, WP0 + 0 * WPK_FLOATS, nullptr,
                                       m1b1, nullptr, nullptr, nullptr, H, n);
    gemm_tc<1, 4><<<nb, NT, SMEM_TC>>>(H, nullptr, WP0 + 1 * WPK_FLOATS, nullptr,
                                       m1b2, nullptr, nullptr, nullptr, X, n);
    // AGG[i] = sum_e vals[e]*X[cols[e]] over rows[e]==i
    gather_kernel<<<(n + 7) / 8, 256>>>(OFF, ECOL, EVAL, X, AGG, n);
    // H = relu(AGG @ m2W1 + b1); OUT = H @ m2W2 + b2
    gemm_tc<0, 4><<<nb, NT, SMEM_TC>>>(AGG, nullptr, WP0 + 2 * WPK_FLOATS, nullptr,
                                       m2b1, nullptr, nullptr, nullptr, H, n);
    gemm_tc<1, 4><<<nb, NT, SMEM_TC>>>(H, nullptr, WP0 + 3 * WPK_FLOATS, nullptr,
                                       m2b2, nullptr, nullptr, nullptr, OUT, n);
    // Z  = sigmoid(OUT@Wu1 + X@Wu2 + bu)
    gemm_tc<2, 8><<<nb, NT, SMEM_TC>>>(OUT, X, WP0 + 4 * WPK_FLOATS, WP0 + 5 * WPK_FLOATS,
                                       bu1, bu2, nullptr, nullptr, Z, n);
    // RX = sigmoid(OUT@Wr1 + X@Wr2 + br) * X
    gemm_tc<2, 8><<<nb, NT, SMEM_TC>>>(OUT, X, WP0 + 6 * WPK_FLOATS, WP0 + 7 * WPK_FLOATS,
                                       br1, br2, X, nullptr, RX, n);
    // y = (1-Z)*X + Z*tanh(OUT@Wo1 + RX@Wo2 + bo)
    gemm_tc<3, 8><<<nb, NT, SMEM_TC>>>(OUT, RX, WP0 + 8 * WPK_FLOATS, WP0 + 9 * WPK_FLOATS,
                                       bo1, bo2, Z, X, y, n);
}

// round 16
// speedup vs baseline: 1.0249x; 1.0249x over previous
#include <cuda_runtime.h>
#include <math.h>
#include <stdint.h>

#define DIM 128
#define MAXN 50000
#define MAXE 1600000
#define BM 128
#define NT 256
// A staging: [4 ks][8 mt][2 g][32 t][4 floats] per buffer = 8192 floats = 32KB
#define AS_FLOATS 8192
#define SMEM_TC (2 * AS_FLOATS * 4)     // 64KB
#define WPK_FLOATS (16 * 16 * 32 * 4)   // one packed weight: 32768 floats

// scratch (device globals; allocation-free rule)
__device__ float g_H  [(size_t)MAXN * DIM];
__device__ float g_X  [(size_t)MAXN * DIM];
__device__ float g_AGG[(size_t)MAXN * DIM];
__device__ float g_OUT[(size_t)MAXN * DIM];
__device__ float g_Z  [(size_t)MAXN * DIM];
__device__ float g_RX [(size_t)MAXN * DIM];
__device__ float g_WP [10 * WPK_FLOATS];
__device__ int   g_off [MAXN + 1];
__device__ int   g_head[MAXN];
__device__ int   g_ecol[MAXE];
__device__ float g_eval[MAXE];

// ---------------- helpers ----------------------------------------------------
__device__ __forceinline__ uint32_t tf32_hi(float x) {
    uint32_t r; asm("cvt.rna.tf32.f32 %0, %1;" : "=r"(r) : "f"(x)); return r;
}
__device__ __forceinline__ void split_tf32(float v, float& h, float& l) {
    uint32_t hb = tf32_hi(v);
    float hf = __uint_as_float(hb);
    h = hf;
    l = __uint_as_float(tf32_hi(v - hf));
}
__device__ __forceinline__ void mma8(float* c,
                                     uint32_t a0, uint32_t a1, uint32_t a2, uint32_t a3,
                                     uint32_t b0, uint32_t b1) {
    asm("mma.sync.aligned.m16n8k8.row.col.f32.tf32.tf32.f32 "
        "{%0,%1,%2,%3}, {%4,%5,%6,%7}, {%8,%9}, {%0,%1,%2,%3};"
        : "+f"(c[0]), "+f"(c[1]), "+f"(c[2]), "+f"(c[3])
        : "r"(a0), "r"(a1), "r"(a2), "r"(a3), "r"(b0), "r"(b1));
}
__device__ __forceinline__ float sigf(float x) { return 1.f / (1.f + __expf(-x)); }

// ---------------- weight pack kernel -----------------------------------------
// W[k][n] (128x128 row-major, k-major) -> fragment order with h/l split.
// item (ks, nt, t): b0 = W[8ks + t%4][8nt + t/4], b1 = W[8ks+4+t%4][8nt + t/4]
// store float4 {b0h, b0l, b1h, b1l} at ((ks*16+nt)*32+t)*4
// grid: (10 weights, 64 slices) x 128 threads -> 4 items/thread... now 2/thread.
struct WPtrs { const float* p[10]; };
__global__ void __launch_bounds__(NT)
pack_w_kernel(WPtrs wp, float* __restrict__ dst) {
    const float* W = wp.p[blockIdx.x];
    float* d = dst + (size_t)blockIdx.x * WPK_FLOATS;
    int base = blockIdx.y * 128;          // 64 slices of 128 items (8192 total)
    for (int s = 0; s < 128; s += NT / 2) {
        // NT=256 threads cover 128 items twice? -> use half threads per pass
        int idx = base + s + (threadIdx.x & 127);
        if ((threadIdx.x >> 7) == (s / (NT / 2)) % 2) {}  // no-op; uniform below
        if (threadIdx.x < 128) {
            idx = base + s + threadIdx.x;
            int t  = idx & 31;
            int nt = (idx >> 5) & 15;
            int ks = idx >> 9;
            int k0 = ks * 8 + (t & 3);
            int n  = nt * 8 + (t >> 2);
            float b0 = W[k0 * DIM + n];
            float b1 = W[(k0 + 4) * DIM + n];
            float h0, l0, h1, l1;
            split_tf32(b0, h0, l0);
            split_tf32(b1, h1, l1);
            *(float4*)(d + (size_t)idx * 4) = make_float4(h0, l0, h1, l1);
        }
    }
}

// ---------------- tensor-core GEMM -------------------------------------------
// C[M x 128] = A[M x K] @ W[K x 128] + epilogue; K = NCH*32 (NCH=4 or 8).
// NCH=8: A=[A0|A1], packed W = [Wp0;Wp1]. 3xTF32: AhBh + AhBl + AlBh.
// 8 warps: wm = warp>>2 (2), wn = warp&3 (4). Warp tile 64(m) x 32(n).
template<int EPI, int NCH>
__global__ void __launch_bounds__(NT, 2)
gemm_tc(const float* __restrict__ A0, const float* __restrict__ A1,
        const float* __restrict__ Wp0, const float* __restrict__ Wp1,
        const float* __restrict__ b1, const float* __restrict__ b2,
        const float* __restrict__ aux1, const float* __restrict__ aux2,
        float* __restrict__ out, int nrows)
{
    extern __shared__ float As[];      // [2][AS_FLOATS]
    const int t = threadIdx.x;
    const int lane = t & 31;
    const int warp = t >> 5;
    const int wm = warp >> 2;          // 0..1
    const int wn = warp & 3;           // 0..3
    const int row0 = blockIdx.x * BM;

    float acc[4][4][4];
    #pragma unroll
    for (int i = 0; i < 4; i++)
        #pragma unroll
        for (int j = 0; j < 4; j++)
            #pragma unroll
            for (int q = 0; q < 4; q++) acc[i][j][q] = 0.f;

    float4 sv[4];

    auto ldA = [&](int cc) {
        const float* src = (NCH == 8 && cc >= 4) ? A1 : A0;
        int kb = ((NCH == 8) ? (cc & 3) : cc) * 32;
        #pragma unroll
        for (int j = 0; j < 4; j++) {
            int idx = t + j * NT;
            int r = idx >> 3;          // 0..127
            int c4 = idx & 7;          // float4 within 32-k chunk
            if (row0 + r < nrows)
                sv[j] = *(const float4*)(src + (size_t)(row0 + r) * DIM + kb + c4 * 4);
            else
                sv[j] = make_float4(0.f, 0.f, 0.f, 0.f);
        }
    };
    auto stsA = [&](int buf) {
        float* d = As + buf * AS_FLOATS;
        #pragma unroll
        for (int j = 0; j < 4; j++) {
            int idx = t + j * NT;
            int r = idx >> 3;
            int c4 = idx & 7;
            int ks = c4 >> 1;          // 0..3
            int g  = c4 & 1;           // k-half within kstep
            int L  = (r & 7) * 4;      // lane base
            int e  = (r >> 3) & 1;     // row-half (a0 vs a1)
            int mt = r >> 4;           // 0..7
            int fbase = (((ks * 8 + mt) * 2 + g) * 32);
            float v[4] = {sv[j].x, sv[j].y, sv[j].z, sv[j].w};
            #pragma unroll
            for (int i = 0; i < 4; i++) {
                float h, l;
                split_tf32(v[i], h, l);
                *(float2*)(d + (size_t)(fbase + L + i) * 4 + e * 2) = make_float2(h, l);
            }
        }
    };

    ldA(0);
    stsA(0);

    for (int cc = 0; cc < NCH; cc++) {
        __syncthreads();
        if (cc + 1 < NCH) ldA(cc + 1);
        const float* sb = As + (cc & 1) * AS_FLOATS;
        const float* Wp = (NCH == 8 && cc >= 4) ? Wp1 : Wp0;
        int ccl = (NCH == 8) ? (cc & 3) : cc;
        #pragma unroll
        for (int ks = 0; ks < 4; ks++) {
            int ksg = ccl * 4 + ks;
            uint4 bq[4];
            #pragma unroll
            for (int nt = 0; nt < 4; nt++)
                bq[nt] = *(const uint4*)(Wp + (size_t)(((ksg * 16 + wn * 4 + nt) * 32 + lane)) * 4);
            #pragma unroll
            for (int mt = 0; mt < 4; mt++) {
                int mt_g = wm * 4 + mt;
                uint4 q0 = *(const uint4*)(sb + (size_t)(((ks * 8 + mt_g) * 2 + 0) * 32 + lane) * 4);
                uint4 q1 = *(const uint4*)(sb + (size_t)(((ks * 8 + mt_g) * 2 + 1) * 32 + lane) * 4);
                #pragma unroll
                for (int nt = 0; nt < 4; nt++) {
                    mma8(acc[mt][nt], q0.x, q0.z, q1.x, q1.z, bq[nt].x, bq[nt].z);   // h*h
                    mma8(acc[mt][nt], q0.x, q0.z, q1.x, q1.z, bq[nt].y, bq[nt].w);   // h*l
                    mma8(acc[mt][nt], q0.y, q0.w, q1.y, q1.w, bq[nt].x, bq[nt].z);   // l*h
                }
            }
        }
        if (cc + 1 < NCH) stsA((cc + 1) & 1);
    }

    // ---------------- epilogue ----------------
    #pragma unroll
    for (int nt = 0; nt < 4; nt++) {
        int col = wn * 32 + nt * 8 + 2 * (lane & 3);
        float2 bb = *(const float2*)(b1 + col);
        if (b2 != nullptr) {
            float2 b2v = *(const float2*)(b2 + col);
            bb.x += b2v.x; bb.y += b2v.y;
        }
        #pragma unroll
        for (int mt = 0; mt < 4; mt++) {
            #pragma unroll
            for (int half = 0; half < 2; half++) {
                int m = row0 + wm * 64 + mt * 16 + (lane >> 2) + half * 8;
                if (m >= nrows) continue;
                float vx = acc[mt][nt][half * 2 + 0] + bb.x;
                float vy = acc[mt][nt][half * 2 + 1] + bb.y;
                float2 o;
                if (EPI == 0) {
                    o = make_float2(fmaxf(vx, 0.f), fmaxf(vy, 0.f));
                } else if (EPI == 1) {
                    o = make_float2(vx, vy);
                } else if (EPI == 2) {
                    o = make_float2(sigf(vx), sigf(vy));
                    if (aux1 != nullptr) {
                        float2 xv = *(const float2*)(aux1 + (size_t)m * DIM + col);
                        o.x *= xv.x; o.y *= xv.y;
                    }
                } else {  // EPI == 3: y = (1-z)*x + z*tanh(v)
                    float2 zv = *(const float2*)(aux1 + (size_t)m * DIM + col);
                    float2 xv = *(const float2*)(aux2 + (size_t)m * DIM + col);
                    o.x = (1.f - zv.x) * xv.x + zv.x * tanhf(vx);
                    o.y = (1.f - zv.y) * xv.y + zv.y * tanhf(vy);
                }
                *(float2*)(out + (size_t)m * DIM + col) = o;
            }
        }
    }
}

// ---------------- CSR build + gather (unchanged, proven) ---------------------
__global__ void hist_kernel(const int* __restrict__ rows, int* __restrict__ cnt, int E) {
    int e = blockIdx.x * blockDim.x + threadIdx.x;
    if (e < E) atomicAdd(&cnt[__ldg(rows + e)], 1);
}

__global__ void __launch_bounds__(1024)
scan_kernel(int* __restrict__ cnt, int* __restrict__ head, int n) {
    __shared__ int wsum[32];
    __shared__ int carry;
    const int tid = threadIdx.x;
    const int lane = tid & 31, w = tid >> 5;
    if (tid == 0) carry = 0;
    __syncthreads();
    for (int base = 0; base < n; base += 1024) {
        int i = base + tid;
        int v = (i < n) ? cnt[i] : 0;
        int x = v;
        #pragma unroll
        for (int d = 1; d < 32; d <<= 1) {
            int y = __shfl_up_sync(~0u, x, d);
            if (lane >= d) x += y;
        }
        if (lane == 31) wsum[w] = x;
        __syncthreads();
        if (w == 0) {
            int s = wsum[lane];
            #pragma unroll
            for (int d = 1; d < 32; d <<= 1) {
                int y = __shfl_up_sync(~0u, s, d);
                if (lane >= d) s += y;
            }
            wsum[lane] = s;
        }
        __syncthreads();
        int incl = x + (w > 0 ? wsum[w - 1] : 0) + carry;
        int excl = incl - v;
        if (i < n) { cnt[i] = excl; head[i] = excl; }
        __syncthreads();
        if (tid == 1023) carry = incl;
        __syncthreads();
    }
    if (tid == 0) cnt[n] = carry;
}

__global__ void bucket_kernel(const int* __restrict__ rows, const int* __restrict__ cols,
                              const float* __restrict__ vals, int* __restrict__ head,
                              int* __restrict__ ecol, float* __restrict__ eval, int E) {
    int e = blockIdx.x * blockDim.x + threadIdx.x;
    if (e < E) {
        int p = atomicAdd(&head[__ldg(rows + e)], 1);
        ecol[p] = __ldg(cols + e);
        eval[p] = __ldg(vals + e);
    }
}

__global__ void __launch_bounds__(256)
gather_kernel(const int* __restrict__ off, const int* __restrict__ ecol,
              const float* __restrict__ eval, const float* __restrict__ X,
              float* __restrict__ AGG, int n)
{
    int node = blockIdx.x * 8 + (threadIdx.x >> 5);
    int lane = threadIdx.x & 31;
    if (node >= n) return;
    int j   = __ldg(off + node);
    int end = __ldg(off + node + 1);
    float4 acc = make_float4(0.f, 0.f, 0.f, 0.f);
    for (; j + 1 < end; j += 2) {
        int   c0 = __ldg(ecol + j),     c1 = __ldg(ecol + j + 1);
        float v0 = __ldg(eval + j),     v1 = __ldg(eval + j + 1);
        float4 x0 = reinterpret_cast<const float4*>(X + (size_t)c0 * DIM)[lane];
        float4 x1 = reinterpret_cast<const float4*>(X + (size_t)c1 * DIM)[lane];
        acc.x = fmaf(v0, x0.x, acc.x); acc.y = fmaf(v0, x0.y, acc.y);
        acc.z = fmaf(v0, x0.z, acc.z); acc.w = fmaf(v0, x0.w, acc.w);
        acc.x = fmaf(v1, x1.x, acc.x); acc.y = fmaf(v1, x1.y, acc.y);
        acc.z = fmaf(v1, x1.z, acc.z); acc.w = fmaf(v1, x1.w, acc.w);
    }
    if (j < end) {
        int   c0 = __ldg(ecol + j);
        float v0 = __ldg(eval + j);
        float4 x0 = reinterpret_cast<const float4*>(X + (size_t)c0 * DIM)[lane];
        acc.x = fmaf(v0, x0.x, acc.x); acc.y = fmaf(v0, x0.y, acc.y);
        acc.z = fmaf(v0, x0.z, acc.z); acc.w = fmaf(v0, x0.w, acc.w);
    }
    reinterpret_cast<float4*>(AGG + (size_t)node * DIM)[lane] = acc;
}

// ---------------- launch -----------------------------------------------------
extern "C" void kernel_launch(void* const* d_in, const int* in_sizes, int n_in,
                              void* d_out, int out_size)
{
    const float* x_in = (const float*)d_in[0];
    const int*   rows = (const int*)d_in[1];
    const int*   cols = (const int*)d_in[2];
    const float* vals = (const float*)d_in[3];
    const float* m1W1 = (const float*)d_in[4];
    const float* m1b1 = (const float*)d_in[5];
    const float* m1W2 = (const float*)d_in[6];
    const float* m1b2 = (const float*)d_in[7];
    const float* m2W1 = (const float*)d_in[8];
    const float* m2b1 = (const float*)d_in[9];
    const float* m2W2 = (const float*)d_in[10];
    const float* m2b2 = (const float*)d_in[11];
    const float* Wu1 = (const float*)d_in[12];
    const float* bu1 = (const float*)d_in[13];
    const float* Wu2 = (const float*)d_in[14];
    const float* bu2 = (const float*)d_in[15];
    const float* Wr1 = (const float*)d_in[16];
    const float* br1 = (const float*)d_in[17];
    const float* Wr2 = (const float*)d_in[18];
    const float* br2 = (const float*)d_in[19];
    const float* Wo1 = (const float*)d_in[20];
    const float* bo1 = (const float*)d_in[21];
    const float* Wo2 = (const float*)d_in[22];
    const float* bo2 = (const float*)d_in[23];

    int n = in_sizes[0] / DIM;
    int E = in_sizes[1];
    float* y = (float*)d_out;

    float *H, *X, *AGG, *OUT, *Z, *RX, *EVAL, *WP;
    int *OFF, *HEAD, *ECOL;
    cudaGetSymbolAddress((void**)&H, g_H);
    cudaGetSymbolAddress((void**)&X, g_X);
    cudaGetSymbolAddress((void**)&AGG, g_AGG);
    cudaGetSymbolAddress((void**)&OUT, g_OUT);
    cudaGetSymbolAddress((void**)&Z, g_Z);
    cudaGetSymbolAddress((void**)&RX, g_RX);
    cudaGetSymbolAddress((void**)&WP, g_WP);
    cudaGetSymbolAddress((void**)&OFF, g_off);
    cudaGetSymbolAddress((void**)&HEAD, g_head);
    cudaGetSymbolAddress((void**)&ECOL, g_ecol);
    cudaGetSymbolAddress((void**)&EVAL, g_eval);

    cudaFuncSetAttribute(gemm_tc<0, 4>, cudaFuncAttributeMaxDynamicSharedMemorySize, SMEM_TC);
    cudaFuncSetAttribute(gemm_tc<1, 4>, cudaFuncAttributeMaxDynamicSharedMemorySize, SMEM_TC);
    cudaFuncSetAttribute(gemm_tc<2, 8>, cudaFuncAttributeMaxDynamicSharedMemorySize, SMEM_TC);
    cudaFuncSetAttribute(gemm_tc<3, 8>, cudaFuncAttributeMaxDynamicSharedMemorySize, SMEM_TC);

    int nb = (n + BM - 1) / BM;
    int eb = (E + 255) / 256;

    WPtrs wp;
    wp.p[0] = m1W1; wp.p[1] = m1W2; wp.p[2] = m2W1; wp.p[3] = m2W2;
    wp.p[4] = Wu1;  wp.p[5] = Wu2;  wp.p[6] = Wr1;  wp.p[7] = Wr2;
    wp.p[8] = Wo1;  wp.p[9] = Wo2;

    // ---- weight pack (wide grid) + CSR build ----
    pack_w_kernel<<<dim3(10, 64), NT>>>(wp, WP);
    cudaMemsetAsync(OFF, 0, (size_t)(n + 1) * sizeof(int));
    hist_kernel<<<eb, 256>>>(rows, OFF, E);
    scan_kernel<<<1, 1024>>>(OFF, HEAD, n);
    bucket_kernel<<<eb, 256>>>(rows, cols, vals, HEAD, ECOL, EVAL, E);

    const float* WP0 = WP;
    // H = relu(x_in @ m1W1 + b1); X = H @ m1W2 + b2
    gemm_tc<0, 4><<<nb, NT, SMEM_TC>>>(x_in, nullptr, WP0 + 0 * WPK_FLOATS, nullptr,
                                       m1b1, nullptr, nullptr, nullptr, H, n);
    gemm_tc<1, 4><<<nb, NT, SMEM_TC>>>(H, nullptr, WP0 + 1 * WPK_FLOATS, nullptr,
                                       m1b2, nullptr, nullptr, nullptr, X, n);
    // AGG[i] = sum_e vals[e]*X[cols[e]] over rows[e]==i
    gather_kernel<<<(n + 7) / 8, 256>>>(OFF, ECOL, EVAL, X, AGG, n);
    // H = relu(AGG @ m2W1 + b1); OUT = H @ m2W2 + b2
    gemm_tc<0, 4><<<nb, NT, SMEM_TC>>>(AGG, nullptr, WP0 + 2 * WPK_FLOATS, nullptr,
                                       m2b1, nullptr, nullptr, nullptr, H, n);
    gemm_tc<1, 4><<<nb, NT, SMEM_TC>>>(H, nullptr, WP0 + 3 * WPK_FLOATS, nullptr,
                                       m2b2, nullptr, nullptr, nullptr, OUT, n);
    // Z  = sigmoid(OUT@Wu1 + X@Wu2 + bu)
    gemm_tc<2, 8><<<nb, NT, SMEM_TC>>>(OUT, X, WP0 + 4 * WPK_FLOATS, WP0 + 5 * WPK_FLOATS,
                                       bu1, bu2, nullptr, nullptr, Z, n);
    // RX = sigmoid(OUT@Wr1 + X@Wr2 + br) * X
    gemm_tc<2, 8><<<nb, NT, SMEM_TC>>>(OUT, X, WP0 + 6 * WPK_FLOATS, WP0 + 7 * WPK_FLOATS,
                                       br1, br2, X, nullptr, RX, n);
    // y = (1-Z)*X + Z*tanh(OUT@Wo1 + RX@Wo2 + bo)
    gemm_tc<3, 8><<<nb, NT, SMEM_TC>>>(OUT, RX, WP0 + 8 * WPK_FLOATS, WP0 + 9 * WPK_FLOATS,
                                       bo1, bo2, Z, X, y, n);
}